// round 3
// baseline (speedup 1.0000x reference)
#include <cuda_runtime.h>
#include <math.h>

#define NN 65536
#define EE 524288

typedef unsigned long long u64;

__device__ __forceinline__ u64 pk(float x, float y) {
    u64 r; asm("mov.b64 %0,{%1,%2};" : "=l"(r) : "f"(x), "f"(y)); return r;
}
__device__ __forceinline__ float2 upk(u64 v) {
    float2 f; asm("mov.b64 {%0,%1},%2;" : "=f"(f.x), "=f"(f.y) : "l"(v)); return f;
}
__device__ __forceinline__ void fma2(u64& a, u64 b, u64 c) {
    asm("fma.rn.f32x2 %0,%1,%2,%0;" : "+l"(a) : "l"(b), "l"(c));
}

// ---------------- scratch ----------------
__device__ float g_q[NN * 64];
__device__ float g_k[NN * 64];
__device__ float g_v[NN * 64];
__device__ float g_attn[NN * 64];
__device__ float g_h1[NN * 64];
__device__ float g_hn2[NN * 64];
__device__ float g_m[NN * 128];
__device__ float g_score[EE * 4];
__device__ float g_WkE[64 * 64];
__device__ float g_WvE[64 * 64];
__device__ float g_bkE[64];
__device__ float g_bvE[64];
__device__ int   g_cnt[NN];
__device__ int   g_cur[NN];
__device__ int   g_rs[NN + 1];
__device__ int   g_elist[EE];

// ---------------- CSR build ----------------
__global__ void k_zero_cnt() {
    int i = blockIdx.x * blockDim.x + threadIdx.x;
    if (i < NN) g_cnt[i] = 0;
}
__global__ void k_count(const int* __restrict__ ei) {
    int e = blockIdx.x * blockDim.x + threadIdx.x;
    if (e < EE) atomicAdd(&g_cnt[ei[EE + e]], 1);
}
__global__ void k_scan() {
    __shared__ int sb[1024];
    int t = threadIdx.x;
    int base = t * 64;
    int s = 0;
    for (int j = 0; j < 64; j++) s += g_cnt[base + j];
    sb[t] = s;
    __syncthreads();
    for (int off = 1; off < 1024; off <<= 1) {
        int v = (t >= off) ? sb[t - off] : 0;
        __syncthreads();
        sb[t] += v;
        __syncthreads();
    }
    int run = sb[t] - s;
    for (int j = 0; j < 64; j++) {
        g_rs[base + j]  = run;
        g_cur[base + j] = run;
        run += g_cnt[base + j];
    }
    if (t == 1023) g_rs[NN] = run;
}
__global__ void k_scatter(const int* __restrict__ ei) {
    int e = blockIdx.x * blockDim.x + threadIdx.x;
    if (e < EE) {
        int d = ei[EE + e];
        int p = atomicAdd(&g_cur[d], 1);
        g_elist[p] = e;
    }
}

// ---------------- prep: fold rotations into Wk/Wv ----------------
__global__ void k_prep(const float* __restrict__ Wk, const float* __restrict__ bk,
                       const float* __restrict__ Wv, const float* __restrict__ bv,
                       const float* __restrict__ ew, const float* __restrict__ mw)
{
    int t = threadIdx.x;  // 256
    #pragma unroll 1
    for (int i = t * 16; i < t * 16 + 16; i++) {
        int d = i >> 6, hc = i & 63, h = hc >> 4, c = hc & 15;
        float sk = 0.f, sv = 0.f;
        #pragma unroll
        for (int d2 = 0; d2 < 16; d2++) {
            sk += Wk[d * 64 + h * 16 + d2] * ew[h * 256 + d2 * 16 + c];
            sv += Wv[d * 64 + h * 16 + d2] * mw[h * 256 + d2 * 16 + c];
        }
        g_WkE[i] = sk; g_WvE[i] = sv;
    }
    if (t < 64) {
        int h = t >> 4, c = t & 15;
        float sk = 0.f, sv = 0.f;
        #pragma unroll
        for (int d2 = 0; d2 < 16; d2++) {
            sk += bk[h * 16 + d2] * ew[h * 256 + d2 * 16 + c];
            sv += bv[h * 16 + d2] * mw[h * 256 + d2 * 16 + c];
        }
        g_bkE[t] = sk; g_bvE[t] = sv;
    }
}

// ---------------- shared helpers ----------------
// smem layout for 64x64 W: [d*80 + q*20 + c], c<16  (q-chunk swizzle, conflict-free)
__device__ __forceinline__ void load_w64(const float* __restrict__ W, float* sW, int t) {
    #pragma unroll 4
    for (int i = t; i < 4096; i += 256) {
        int d = i >> 6, c = i & 63;
        sW[d * 80 + (c >> 4) * 20 + (c & 15)] = W[i];
    }
}

// 16-output GEMV over K=64: row in smem (stride given by caller ptr), sWq = sW + q*20
__device__ __forceinline__ void gemv16_64(const float* __restrict__ row,
                                          const float* __restrict__ sWq, u64 acc[8]) {
    #pragma unroll
    for (int d4 = 0; d4 < 16; d4++) {
        float4 a4 = *(const float4*)&row[d4 * 4];
        #pragma unroll
        for (int j = 0; j < 4; j++) {
            float a = (&a4.x)[j];
            u64 a2 = pk(a, a);
            const ulonglong2* w = (const ulonglong2*)&sWq[(d4 * 4 + j) * 80];
            ulonglong2 w0 = w[0], w1 = w[1], w2 = w[2], w3 = w[3];
            fma2(acc[0], a2, w0.x); fma2(acc[1], a2, w0.y);
            fma2(acc[2], a2, w1.x); fma2(acc[3], a2, w1.y);
            fma2(acc[4], a2, w2.x); fma2(acc[5], a2, w2.y);
            fma2(acc[6], a2, w3.x); fma2(acc[7], a2, w3.y);
        }
    }
}

#define TS 68   // tile row stride (words) for 64-wide rows

// ---------------- generic: LN(in-row) then GEMV64 -> out ----------------
__global__ __launch_bounds__(256) void k_gemv_ln(
    const float* __restrict__ in, const float* __restrict__ W,
    const float* __restrict__ bias, const float* __restrict__ lg,
    const float* __restrict__ lb, float* __restrict__ outp)
{
    extern __shared__ float sm[];
    float* sW = sm;            // 5120
    float* sP = sW + 5120;     // 192
    float* tile = sP + 192;    // 64*TS

    int t = threadIdx.x;
    load_w64(W, sW, t);
    if (t < 64) { sP[t] = bias[t]; sP[64 + t] = lg[t]; sP[128 + t] = lb[t]; }
    int lane = t & 31;
    int r = ((t >> 5) << 3) + (lane >> 2);
    int q = lane & 3;
    int n = (blockIdx.x << 6) + r;

    float4 v0 = *(const float4*)&in[n * 64 + q * 16 + 0];
    float4 v1 = *(const float4*)&in[n * 64 + q * 16 + 4];
    float4 v2 = *(const float4*)&in[n * 64 + q * 16 + 8];
    float4 v3 = *(const float4*)&in[n * 64 + q * 16 + 12];
    float s = 0.f, ss = 0.f;
    float vv[16] = {v0.x,v0.y,v0.z,v0.w, v1.x,v1.y,v1.z,v1.w,
                    v2.x,v2.y,v2.z,v2.w, v3.x,v3.y,v3.z,v3.w};
    #pragma unroll
    for (int i = 0; i < 16; i++) { s += vv[i]; ss += vv[i] * vv[i]; }
    s  += __shfl_xor_sync(0xffffffffu, s, 1);  ss += __shfl_xor_sync(0xffffffffu, ss, 1);
    s  += __shfl_xor_sync(0xffffffffu, s, 2);  ss += __shfl_xor_sync(0xffffffffu, ss, 2);
    float mu = s * (1.0f / 64.0f);
    float inv = rsqrtf(ss * (1.0f / 64.0f) - mu * mu + 1e-5f);
    __syncthreads();
    #pragma unroll
    for (int i = 0; i < 16; i++)
        vv[i] = (vv[i] - mu) * inv * sP[64 + q * 16 + i] + sP[128 + q * 16 + i];
    float4* tp = (float4*)&tile[r * TS + q * 16];
    tp[0] = make_float4(vv[0], vv[1], vv[2], vv[3]);
    tp[1] = make_float4(vv[4], vv[5], vv[6], vv[7]);
    tp[2] = make_float4(vv[8], vv[9], vv[10], vv[11]);
    tp[3] = make_float4(vv[12], vv[13], vv[14], vv[15]);
    __syncthreads();

    u64 acc[8];
    #pragma unroll
    for (int j = 0; j < 8; j++) acc[j] = pk(sP[q * 16 + 2 * j], sP[q * 16 + 2 * j + 1]);
    gemv16_64(&tile[r * TS], sW + q * 20, acc);

    ulonglong2* op = (ulonglong2*)&outp[n * 64 + q * 16];
    op[0] = make_ulonglong2(acc[0], acc[1]);
    op[1] = make_ulonglong2(acc[2], acc[3]);
    op[2] = make_ulonglong2(acc[4], acc[5]);
    op[3] = make_ulonglong2(acc[6], acc[7]);
}

// ---------------- k_edge: LN(ea) -> e-proj -> scores ----------------
__global__ __launch_bounds__(256) void k_edge(
    const float* __restrict__ ea, const int* __restrict__ ei,
    const float* __restrict__ We, const float* __restrict__ be,
    const float* __restrict__ lg, const float* __restrict__ lb,
    const float* __restrict__ attn_bi)
{
    extern __shared__ float sm[];
    float* sW = sm;            // 5120
    float* sP = sW + 5120;     // 200
    float* tile = sP + 200;    // 64*TS

    int t = threadIdx.x;
    load_w64(We, sW, t);
    if (t < 64) { sP[t] = be[t]; sP[64 + t] = lg[t]; sP[128 + t] = lb[t]; }
    if (t < 4)  sP[196 + t] = attn_bi[t * 2];
    int lane = t & 31;
    int r = ((t >> 5) << 3) + (lane >> 2);
    int q = lane & 3;
    int e = (blockIdx.x << 6) + r;

    float4 v0 = *(const float4*)&ea[e * 64 + q * 16 + 0];
    float4 v1 = *(const float4*)&ea[e * 64 + q * 16 + 4];
    float4 v2 = *(const float4*)&ea[e * 64 + q * 16 + 8];
    float4 v3 = *(const float4*)&ea[e * 64 + q * 16 + 12];
    float vv[16] = {v0.x,v0.y,v0.z,v0.w, v1.x,v1.y,v1.z,v1.w,
                    v2.x,v2.y,v2.z,v2.w, v3.x,v3.y,v3.z,v3.w};
    float s = 0.f, ss = 0.f;
    #pragma unroll
    for (int i = 0; i < 16; i++) { s += vv[i]; ss += vv[i] * vv[i]; }
    s  += __shfl_xor_sync(0xffffffffu, s, 1);  ss += __shfl_xor_sync(0xffffffffu, ss, 1);
    s  += __shfl_xor_sync(0xffffffffu, s, 2);  ss += __shfl_xor_sync(0xffffffffu, ss, 2);
    float mu = s * (1.0f / 64.0f);
    float inv = rsqrtf(ss * (1.0f / 64.0f) - mu * mu + 1e-5f);
    __syncthreads();
    #pragma unroll
    for (int i = 0; i < 16; i++)
        vv[i] = (vv[i] - mu) * inv * sP[64 + q * 16 + i] + sP[128 + q * 16 + i];
    float4* tp = (float4*)&tile[r * TS + q * 16];
    tp[0] = make_float4(vv[0], vv[1], vv[2], vv[3]);
    tp[1] = make_float4(vv[4], vv[5], vv[6], vv[7]);
    tp[2] = make_float4(vv[8], vv[9], vv[10], vv[11]);
    tp[3] = make_float4(vv[12], vv[13], vv[14], vv[15]);
    __syncthreads();

    u64 acc[8];
    #pragma unroll
    for (int j = 0; j < 8; j++) acc[j] = pk(sP[q * 16 + 2 * j], sP[q * 16 + 2 * j + 1]);
    gemv16_64(&tile[r * TS], sW + q * 20, acc);
    float evv[16];
    #pragma unroll
    for (int j = 0; j < 8; j++) { float2 f = upk(acc[j]); evv[2*j] = f.x; evv[2*j+1] = f.y; }

    int src = ei[e];
    int dst = ei[EE + e];
    const float4* qp = (const float4*)&g_q[dst * 64 + q * 16];
    const float4* kp = (const float4*)&g_k[src * 64 + q * 16];
    float dot = 0.f;
    #pragma unroll
    for (int i4 = 0; i4 < 4; i4++) {
        float4 q4 = qp[i4];
        float4 k4 = kp[i4];
        dot += q4.x * k4.x * evv[i4*4+0];
        dot += q4.y * k4.y * evv[i4*4+1];
        dot += q4.z * k4.z * evv[i4*4+2];
        dot += q4.w * k4.w * evv[i4*4+3];
    }
    g_score[e * 4 + q] = dot * 0.25f + sP[196 + q];
}

// ---------------- k_attn: segment softmax + weighted gather ----------------
__global__ __launch_bounds__(256) void k_attn(const int* __restrict__ ei)
{
    int gw   = (blockIdx.x * blockDim.x + threadIdx.x) >> 5;
    int lane = threadIdx.x & 31;
    if (gw >= NN) return;
    int start = g_rs[gw], end = g_rs[gw + 1];

    const float NEG = __int_as_float(0xff800000);
    float m0 = NEG, m1 = NEG, m2 = NEG, m3 = NEG;
    for (int i = start + lane; i < end; i += 32) {
        float4 sc = ((const float4*)&g_score[g_elist[i] * 4])[0];
        m0 = fmaxf(m0, sc.x); m1 = fmaxf(m1, sc.y);
        m2 = fmaxf(m2, sc.z); m3 = fmaxf(m3, sc.w);
    }
    #pragma unroll
    for (int o = 16; o; o >>= 1) {
        m0 = fmaxf(m0, __shfl_xor_sync(0xffffffffu, m0, o));
        m1 = fmaxf(m1, __shfl_xor_sync(0xffffffffu, m1, o));
        m2 = fmaxf(m2, __shfl_xor_sync(0xffffffffu, m2, o));
        m3 = fmaxf(m3, __shfl_xor_sync(0xffffffffu, m3, o));
    }
    float s0 = 0.f, s1 = 0.f, s2 = 0.f, s3 = 0.f;
    for (int i = start + lane; i < end; i += 32) {
        float4 sc = ((const float4*)&g_score[g_elist[i] * 4])[0];
        s0 += __expf(sc.x - m0); s1 += __expf(sc.y - m1);
        s2 += __expf(sc.z - m2); s3 += __expf(sc.w - m3);
    }
    #pragma unroll
    for (int o = 16; o; o >>= 1) {
        s0 += __shfl_xor_sync(0xffffffffu, s0, o);
        s1 += __shfl_xor_sync(0xffffffffu, s1, o);
        s2 += __shfl_xor_sync(0xffffffffu, s2, o);
        s3 += __shfl_xor_sync(0xffffffffu, s3, o);
    }

    int   h0  = lane >> 4;
    float mh0 = h0 ? m1 : m0;
    float mh1 = h0 ? m3 : m2;
    float a0 = 0.f, a1 = 0.f;
    for (int i = start; i < end; i++) {
        int e   = g_elist[i];
        int src = ei[e];
        float w0 = __expf(g_score[e * 4 + h0]     - mh0);
        float w1 = __expf(g_score[e * 4 + 2 + h0] - mh1);
        a0 += w0 * g_v[src * 64 + lane];
        a1 += w1 * g_v[src * 64 + 32 + lane];
    }
    float d0 = (h0 ? s1 : s0) + 1e-16f;
    float d1 = (h0 ? s3 : s2) + 1e-16f;
    g_attn[gw * 64 + lane]      = a0 / d0;
    g_attn[gw * 64 + 32 + lane] = a1 / d1;
}

// ---------------- k_final1: Wo + gated residual + LN2 ----------------
__global__ __launch_bounds__(256) void k_final1(
    const float* __restrict__ x,
    const float* __restrict__ Wo, const float* __restrict__ bo,
    const float* __restrict__ skip,
    const float* __restrict__ lg, const float* __restrict__ lb)
{
    extern __shared__ float sm[];
    float* sW = sm;            // 5120
    float* sP = sW + 5120;     // 192
    float* tile = sP + 192;    // 64*TS

    int t = threadIdx.x;
    load_w64(Wo, sW, t);
    if (t < 64) { sP[t] = bo[t]; sP[64 + t] = lg[t]; sP[128 + t] = lb[t]; }
    int lane = t & 31;
    int r = ((t >> 5) << 3) + (lane >> 2);
    int q = lane & 3;
    int n = (blockIdx.x << 6) + r;

    float4* tp = (float4*)&tile[r * TS + q * 16];
    const float4* ap = (const float4*)&g_attn[n * 64 + q * 16];
    tp[0] = ap[0]; tp[1] = ap[1]; tp[2] = ap[2]; tp[3] = ap[3];
    __syncthreads();

    u64 acc[8];
    #pragma unroll
    for (int j = 0; j < 8; j++) acc[j] = pk(sP[q * 16 + 2 * j], sP[q * 16 + 2 * j + 1]);
    gemv16_64(&tile[r * TS], sW + q * 20, acc);

    float gg = 1.0f / (1.0f + __expf(-skip[0]));
    const float4* xp = (const float4*)&x[n * 64 + q * 16];
    float h1[16];
    #pragma unroll
    for (int j = 0; j < 8; j++) {
        float2 f = upk(acc[j]);
        float4 xx = ((j & 1) == 0) ? xp[j >> 1] : xp[j >> 1];
        // load x pairwise
        h1[2*j]   = gg * f.x;
        h1[2*j+1] = gg * f.y;
    }
    {
        float4 x0 = xp[0], x1 = xp[1], x2 = xp[2], x3 = xp[3];
        float xs[16] = {x0.x,x0.y,x0.z,x0.w, x1.x,x1.y,x1.z,x1.w,
                        x2.x,x2.y,x2.z,x2.w, x3.x,x3.y,x3.z,x3.w};
        #pragma unroll
        for (int i = 0; i < 16; i++) h1[i] += (1.0f - gg) * xs[i];
    }
    // store h1
    float4* hp = (float4*)&g_h1[n * 64 + q * 16];
    hp[0] = make_float4(h1[0], h1[1], h1[2], h1[3]);
    hp[1] = make_float4(h1[4], h1[5], h1[6], h1[7]);
    hp[2] = make_float4(h1[8], h1[9], h1[10], h1[11]);
    hp[3] = make_float4(h1[12], h1[13], h1[14], h1[15]);
    // LN2
    float s = 0.f, ssum = 0.f;
    #pragma unroll
    for (int i = 0; i < 16; i++) { s += h1[i]; ssum += h1[i] * h1[i]; }
    s += __shfl_xor_sync(0xffffffffu, s, 1);  ssum += __shfl_xor_sync(0xffffffffu, ssum, 1);
    s += __shfl_xor_sync(0xffffffffu, s, 2);  ssum += __shfl_xor_sync(0xffffffffu, ssum, 2);
    float mu = s * (1.0f / 64.0f);
    float inv = rsqrtf(ssum * (1.0f / 64.0f) - mu * mu + 1e-5f);
    float hn[16];
    #pragma unroll
    for (int i = 0; i < 16; i++)
        hn[i] = (h1[i] - mu) * inv * sP[64 + q * 16 + i] + sP[128 + q * 16 + i];
    float4* gp = (float4*)&g_hn2[n * 64 + q * 16];
    gp[0] = make_float4(hn[0], hn[1], hn[2], hn[3]);
    gp[1] = make_float4(hn[4], hn[5], hn[6], hn[7]);
    gp[2] = make_float4(hn[8], hn[9], hn[10], hn[11]);
    gp[3] = make_float4(hn[12], hn[13], hn[14], hn[15]);
}

// ---------------- k_ffn1: m = relu(hn2 @ W1 + b1) ----------------
// W1 smem layout: [d*144 + q*36 + c], c<32
__global__ __launch_bounds__(256) void k_ffn1(
    const float* __restrict__ W1, const float* __restrict__ b1)
{
    extern __shared__ float sm[];
    float* sW = sm;            // 9216
    float* sP = sW + 9216;     // 128
    float* tile = sP + 128;    // 64*TS

    int t = threadIdx.x;
    #pragma unroll 4
    for (int i = t; i < 8192; i += 256) {
        int d = i >> 7, c = i & 127;
        sW[d * 144 + (c >> 5) * 36 + (c & 31)] = W1[i];
    }
    if (t < 128) sP[t] = b1[t];
    int lane = t & 31;
    int r = ((t >> 5) << 3) + (lane >> 2);
    int q = lane & 3;
    int n = (blockIdx.x << 6) + r;

    float4* tp = (float4*)&tile[r * TS + q * 16];
    const float4* ip = (const float4*)&g_hn2[n * 64 + q * 16];
    tp[0] = ip[0]; tp[1] = ip[1]; tp[2] = ip[2]; tp[3] = ip[3];
    __syncthreads();

    u64 acc[16];
    #pragma unroll
    for (int j = 0; j < 16; j++) acc[j] = pk(sP[q * 32 + 2 * j], sP[q * 32 + 2 * j + 1]);
    const float* row = &tile[r * TS];
    const float* sWq = sW + q * 36;
    #pragma unroll
    for (int d4 = 0; d4 < 16; d4++) {
        float4 a4 = *(const float4*)&row[d4 * 4];
        #pragma unroll
        for (int j = 0; j < 4; j++) {
            float a = (&a4.x)[j];
            u64 a2 = pk(a, a);
            const ulonglong2* w = (const ulonglong2*)&sWq[(d4 * 4 + j) * 144];
            #pragma unroll
            for (int k = 0; k < 8; k++) {
                ulonglong2 ww = w[k];
                fma2(acc[2*k],   a2, ww.x);
                fma2(acc[2*k+1], a2, ww.y);
            }
        }
    }
    float4* mp = (float4*)&g_m[n * 128 + q * 32];
    #pragma unroll
    for (int k = 0; k < 8; k++) {
        float2 f0 = upk(acc[2*k]);
        float2 f1 = upk(acc[2*k+1]);
        mp[k] = make_float4(fmaxf(f0.x, 0.f), fmaxf(f0.y, 0.f),
                            fmaxf(f1.x, 0.f), fmaxf(f1.y, 0.f));
    }
}

// ---------------- k_ffn2: out = h1 + m @ W2 + b2 ----------------
// W2 smem layout: [m*80 + q*20 + c], c<16 ; m-tile stride 132
#define TS2 132
__global__ __launch_bounds__(256) void k_ffn2(
    const float* __restrict__ W2, const float* __restrict__ b2,
    float* __restrict__ outp)
{
    extern __shared__ float sm[];
    float* sW = sm;            // 10240
    float* sP = sW + 10240;    // 64
    float* tile = sP + 64;     // 64*TS2

    int t = threadIdx.x;
    #pragma unroll 4
    for (int i = t; i < 8192; i += 256) {
        int m = i >> 6, c = i & 63;
        sW[m * 80 + (c >> 4) * 20 + (c & 15)] = W2[i];
    }
    if (t < 64) sP[t] = b2[t];
    int lane = t & 31;
    int r = ((t >> 5) << 3) + (lane >> 2);
    int q = lane & 3;
    int n = (blockIdx.x << 6) + r;

    float4* tp = (float4*)&tile[r * TS2 + q * 32];
    const float4* ip = (const float4*)&g_m[n * 128 + q * 32];
    #pragma unroll
    for (int k = 0; k < 8; k++) tp[k] = ip[k];
    __syncthreads();

    // init: h1 + b2
    const float4* hp = (const float4*)&g_h1[n * 64 + q * 16];
    float4 h0 = hp[0], h1v = hp[1], h2 = hp[2], h3 = hp[3];
    float hs[16] = {h0.x,h0.y,h0.z,h0.w, h1v.x,h1v.y,h1v.z,h1v.w,
                    h2.x,h2.y,h2.z,h2.w, h3.x,h3.y,h3.z,h3.w};
    u64 acc[8];
    #pragma unroll
    for (int j = 0; j < 8; j++)
        acc[j] = pk(hs[2*j] + sP[q*16 + 2*j], hs[2*j+1] + sP[q*16 + 2*j+1]);

    const float* row = &tile[r * TS2];
    const float* sWq = sW + q * 20;
    #pragma unroll 8
    for (int d4 = 0; d4 < 32; d4++) {
        float4 a4 = *(const float4*)&row[d4 * 4];
        #pragma unroll
        for (int j = 0; j < 4; j++) {
            float a = (&a4.x)[j];
            u64 a2 = pk(a, a);
            const ulonglong2* w = (const ulonglong2*)&sWq[(d4 * 4 + j) * 80];
            ulonglong2 w0 = w[0], w1 = w[1], w2 = w[2], w3 = w[3];
            fma2(acc[0], a2, w0.x); fma2(acc[1], a2, w0.y);
            fma2(acc[2], a2, w1.x); fma2(acc[3], a2, w1.y);
            fma2(acc[4], a2, w2.x); fma2(acc[5], a2, w2.y);
            fma2(acc[6], a2, w3.x); fma2(acc[7], a2, w3.y);
        }
    }
    ulonglong2* op = (ulonglong2*)&outp[n * 64 + q * 16];
    op[0] = make_ulonglong2(acc[0], acc[1]);
    op[1] = make_ulonglong2(acc[2], acc[3]);
    op[2] = make_ulonglong2(acc[4], acc[5]);
    op[3] = make_ulonglong2(acc[6], acc[7]);
}

// ---------------- launch ----------------
extern "C" void kernel_launch(void* const* d_in, const int* in_sizes, int n_in,
                              void* d_out, int out_size)
{
    const float* x    = (const float*)d_in[0];
    const int*   ei   = (const int*)  d_in[1];
    const float* ea   = (const float*)d_in[2];
    const float* Wq   = (const float*)d_in[3];
    const float* bq   = (const float*)d_in[4];
    const float* Wk   = (const float*)d_in[5];
    const float* bk   = (const float*)d_in[6];
    const float* Wv   = (const float*)d_in[7];
    const float* bv   = (const float*)d_in[8];
    const float* We   = (const float*)d_in[9];
    const float* be   = (const float*)d_in[10];
    const float* Wo   = (const float*)d_in[11];
    const float* bo   = (const float*)d_in[12];
    const float* edge_w = (const float*)d_in[13];
    const float* msg_w  = (const float*)d_in[14];
    const float* skip   = (const float*)d_in[15];
    const float* ln1g = (const float*)d_in[16];
    const float* ln1b = (const float*)d_in[17];
    const float* lneg = (const float*)d_in[18];
    const float* lneb = (const float*)d_in[19];
    const float* ln2g = (const float*)d_in[20];
    const float* ln2b = (const float*)d_in[21];
    const float* W1   = (const float*)d_in[22];
    const float* b1   = (const float*)d_in[23];
    const float* W2   = (const float*)d_in[24];
    const float* b2   = (const float*)d_in[25];
    const float* attn_bi = (const float*)d_in[26];
    float* out = (float*)d_out;

    // resolve __device__ symbols
    static float *p_WkE = nullptr, *p_WvE = nullptr, *p_bkE = nullptr, *p_bvE = nullptr;
    if (!p_WkE) {
        cudaGetSymbolAddress((void**)&p_WkE, g_WkE);
        cudaGetSymbolAddress((void**)&p_WvE, g_WvE);
        cudaGetSymbolAddress((void**)&p_bkE, g_bkE);
        cudaGetSymbolAddress((void**)&p_bvE, g_bvE);
    }
    static float *p_q = nullptr, *p_k = nullptr, *p_v = nullptr;
    if (!p_q) {
        cudaGetSymbolAddress((void**)&p_q, g_q);
        cudaGetSymbolAddress((void**)&p_k, g_k);
        cudaGetSymbolAddress((void**)&p_v, g_v);
    }

    size_t sm_g  = (size_t)(5120 + 192 + 64 * TS) * sizeof(float);
    size_t sm_e  = (size_t)(5120 + 200 + 64 * TS) * sizeof(float);
    size_t sm_f1 = (size_t)(5120 + 192 + 64 * TS) * sizeof(float);
    size_t sm_n1 = (size_t)(9216 + 128 + 64 * TS) * sizeof(float);
    size_t sm_n2 = (size_t)(10240 + 64 + 64 * TS2) * sizeof(float);
    cudaFuncSetAttribute(k_gemv_ln, cudaFuncAttributeMaxDynamicSharedMemorySize, (int)sm_g);
    cudaFuncSetAttribute(k_edge,    cudaFuncAttributeMaxDynamicSharedMemorySize, (int)sm_e);
    cudaFuncSetAttribute(k_final1,  cudaFuncAttributeMaxDynamicSharedMemorySize, (int)sm_f1);
    cudaFuncSetAttribute(k_ffn1,    cudaFuncAttributeMaxDynamicSharedMemorySize, (int)sm_n1);
    cudaFuncSetAttribute(k_ffn2,    cudaFuncAttributeMaxDynamicSharedMemorySize, (int)sm_n2);

    // CSR build
    k_zero_cnt<<<NN / 256, 256>>>();
    k_count<<<EE / 256, 256>>>(ei);
    k_scan<<<1, 1024>>>();
    k_scatter<<<EE / 256, 256>>>(ei);

    // weight prep (fold rotations)
    k_prep<<<1, 256>>>(Wk, bk, Wv, bv, edge_w, msg_w);

    // node projections (LN(x) fused)
    k_gemv_ln<<<NN / 64, 256, sm_g>>>(x, Wq,    bq,    ln1g, ln1b, p_q);
    k_gemv_ln<<<NN / 64, 256, sm_g>>>(x, p_WkE, p_bkE, ln1g, ln1b, p_k);
    k_gemv_ln<<<NN / 64, 256, sm_g>>>(x, p_WvE, p_bvE, ln1g, ln1b, p_v);

    // edge projection + scores
    k_edge<<<EE / 64, 256, sm_e>>>(ea, ei, We, be, lneg, lneb, attn_bi);

    // segment softmax + gather
    k_attn<<<(NN * 32) / 256, 256>>>(ei);

    // output proj + residual + LN2, then FFN
    k_final1<<<NN / 64, 256, sm_f1>>>(x, Wo, bo, skip, ln2g, ln2b);
    k_ffn1<<<NN / 64, 256, sm_n1>>>(W1, b1);
    k_ffn2<<<NN / 64, 256, sm_n2>>>(W2, b2, out);
}

// round 5
// speedup vs baseline: 1.3478x; 1.3478x over previous
#include <cuda_runtime.h>
#include <math.h>

#define NN 65536
#define EE 524288
typedef unsigned long long u64;

__device__ __forceinline__ u64 pk(float x, float y) { u64 r; asm("mov.b64 %0,{%1,%2};" : "=l"(r) : "f"(x), "f"(y)); return r; }
__device__ __forceinline__ float2 upk(u64 v) { float2 f; asm("mov.b64 {%0,%1},%2;" : "=f"(f.x), "=f"(f.y) : "l"(v)); return f; }
__device__ __forceinline__ void fma2(u64& a, u64 b, u64 c) { asm("fma.rn.f32x2 %0,%1,%2,%0;" : "+l"(a) : "l"(b), "l"(c)); }
// interleaved col position within a 64-col weight row (stride-72 smem rows)
__device__ __forceinline__ int wpos(int c) { return ((c & 4) << 3) | ((c >> 3) << 2) | (c & 3); }

// ---------------- scratch ----------------
__device__ float g_q[NN * 64];
__device__ float g_k[NN * 64];
__device__ float g_v[NN * 64];
__device__ float g_attn[NN * 64];
__device__ float g_h1[NN * 64];
__device__ float g_m[NN * 128];
__device__ float g_score[EE * 4];
__device__ float g_WkE[64 * 64];
__device__ float g_WvE[64 * 64];
__device__ float g_bkE[64];
__device__ float g_bvE[64];
__device__ int   g_cnt[NN];
__device__ int   g_cur[NN];
__device__ int   g_rs[NN + 1];
__device__ int   g_elist[EE];

// ---------------- CSR ----------------
__global__ void k_zero_cnt() { int i = blockIdx.x * 256 + threadIdx.x; if (i < NN) g_cnt[i] = 0; }
__global__ void k_count(const int* __restrict__ ei) {
    int e = blockIdx.x * 256 + threadIdx.x;
    if (e < EE) atomicAdd(&g_cnt[ei[EE + e]], 1);
}
__global__ void k_scan() {
    __shared__ int sb[1024];
    int t = threadIdx.x, base = t * 64, s = 0;
    for (int j = 0; j < 64; j++) s += g_cnt[base + j];
    sb[t] = s;
    __syncthreads();
    for (int off = 1; off < 1024; off <<= 1) {
        int v = (t >= off) ? sb[t - off] : 0;
        __syncthreads(); sb[t] += v; __syncthreads();
    }
    int run = sb[t] - s;
    for (int j = 0; j < 64; j++) { g_rs[base + j] = run; g_cur[base + j] = run; run += g_cnt[base + j]; }
    if (t == 1023) g_rs[NN] = run;
}
__global__ void k_scatter(const int* __restrict__ ei) {
    int e = blockIdx.x * 256 + threadIdx.x;
    if (e < EE) { int d = ei[EE + e]; g_elist[atomicAdd(&g_cur[d], 1)] = e; }
}

// ---------------- prep: fold head rotations into Wk/Wv ----------------
__global__ void k_prep(const float* __restrict__ Wk, const float* __restrict__ bk,
                       const float* __restrict__ Wv, const float* __restrict__ bv,
                       const float* __restrict__ ew, const float* __restrict__ mw) {
    int t = threadIdx.x;
    for (int i = t * 16; i < t * 16 + 16; i++) {
        int d = i >> 6, hc = i & 63, h = hc >> 4, c = hc & 15;
        float sk = 0.f, sv = 0.f;
        #pragma unroll
        for (int d2 = 0; d2 < 16; d2++) {
            sk += Wk[d * 64 + h * 16 + d2] * ew[h * 256 + d2 * 16 + c];
            sv += Wv[d * 64 + h * 16 + d2] * mw[h * 256 + d2 * 16 + c];
        }
        g_WkE[i] = sk; g_WvE[i] = sv;
    }
    if (t < 64) {
        int h = t >> 4, c = t & 15;
        float sk = 0.f, sv = 0.f;
        #pragma unroll
        for (int d2 = 0; d2 < 16; d2++) {
            sk += bk[h * 16 + d2] * ew[h * 256 + d2 * 16 + c];
            sv += bv[h * 16 + d2] * mw[h * 256 + d2 * 16 + c];
        }
        g_bkE[t] = sk; g_bvE[t] = sv;
    }
}

// ---------------- 8x8 register-tile GEMM helpers ----------------
__device__ __forceinline__ void init8x8(const float* b, u64 acc[8][4]) {
    #pragma unroll
    for (int cp = 0; cp < 4; cp++) {
        u64 bi = pk(b[2 * cp], b[2 * cp + 1]);
        #pragma unroll
        for (int r = 0; r < 8; r++) acc[r][cp] = bi;
    }
}
template <int K, int AS, int WS>
__device__ __forceinline__ void gemm8x8(const float* __restrict__ a_t,
                                        const float* __restrict__ sWb, int r0, u64 acc[8][4]) {
    #pragma unroll 4
    for (int d = 0; d < K; d++) {
        ulonglong2 wA = *(const ulonglong2*)(sWb + d * WS);
        ulonglong2 wB = *(const ulonglong2*)(sWb + d * WS + 32);
        float4 aA = *(const float4*)(a_t + d * AS + r0);
        float4 aB = *(const float4*)(a_t + d * AS + r0 + 4);
        float av[8] = {aA.x, aA.y, aA.z, aA.w, aB.x, aB.y, aB.z, aB.w};
        #pragma unroll
        for (int r = 0; r < 8; r++) {
            u64 a2 = pk(av[r], av[r]);
            fma2(acc[r][0], a2, wA.x);
            fma2(acc[r][1], a2, wA.y);
            fma2(acc[r][2], a2, wB.x);
            fma2(acc[r][3], a2, wB.y);
        }
    }
}
__device__ __forceinline__ void store8x8(float* base, int rstride, int r0, u64 acc[8][4]) {
    #pragma unroll
    for (int r = 0; r < 8; r++) {
        ulonglong2* o = (ulonglong2*)(base + (size_t)(r0 + r) * rstride);
        o[0] = make_ulonglong2(acc[r][0], acc[r][1]);
        o[1] = make_ulonglong2(acc[r][2], acc[r][3]);
    }
}
// per-thread row LN -> transposed smem tile (column t)
__device__ __forceinline__ void ln_transpose(const float* __restrict__ in, int n, int t,
                                             const float* g, const float* b, float* a_t) {
    const float4* xp = (const float4*)(in + (size_t)n * 64);
    float v[64];
    #pragma unroll
    for (int i = 0; i < 16; i++) { float4 f = xp[i]; v[4*i] = f.x; v[4*i+1] = f.y; v[4*i+2] = f.z; v[4*i+3] = f.w; }
    float s = 0.f, ss = 0.f;
    #pragma unroll
    for (int i = 0; i < 64; i++) { s += v[i]; ss += v[i] * v[i]; }
    float mu = s * 0.015625f;
    float inv = rsqrtf(ss * 0.015625f - mu * mu + 1e-5f);
    #pragma unroll
    for (int d = 0; d < 64; d++) a_t[d * 132 + t] = (v[d] - mu) * inv * g[d] + b[d];
}

// ---------------- K1: node LN + merged QKV (rotations folded) ----------------
__global__ __launch_bounds__(128) void k_node(
    const float* __restrict__ x, const float* __restrict__ Wq, const float* __restrict__ bq,
    const float* __restrict__ ln1g, const float* __restrict__ ln1b) {
    extern __shared__ float sm[];
    float* sW = sm;            // 3*4608
    float* sP = sW + 13824;    // 320
    float* a_t = sP + 320;     // 64*132 = 8448
    int t = threadIdx.x;
    for (int i = t; i < 4096; i += 128) {
        int d = i >> 6, c = i & 63, p = d * 72 + wpos(c);
        sW[p] = Wq[i]; sW[4608 + p] = g_WkE[i]; sW[9216 + p] = g_WvE[i];
    }
    if (t < 64) { sP[t] = bq[t]; sP[64+t] = g_bkE[t]; sP[128+t] = g_bvE[t]; sP[192+t] = ln1g[t]; sP[256+t] = ln1b[t]; }
    __syncthreads();
    int nb = blockIdx.x << 7;
    ln_transpose(x, nb + t, t, sP + 192, sP + 256, a_t);
    __syncthreads();
    int lane = t & 31, wrp = t >> 5, cg = lane & 7, rgl = lane >> 3;
    int r0 = (wrp * 4 + rgl) * 8;
    float* outs[3] = {g_q, g_k, g_v};
    #pragma unroll 1
    for (int ch = 0; ch < 3; ch++) {
        u64 acc[8][4];
        init8x8(&sP[ch * 64 + cg * 8], acc);
        gemm8x8<64, 132, 72>(a_t, sW + ch * 4608 + cg * 4, r0, acc);
        store8x8(outs[ch] + (size_t)nb * 64 + cg * 8, 64, r0, acc);
    }
}

// ---------------- K2: edge LN + e-proj GEMM + scores ----------------
__global__ __launch_bounds__(128) void k_edge(
    const float* __restrict__ ea, const int* __restrict__ ei,
    const float* __restrict__ We, const float* __restrict__ be,
    const float* __restrict__ lneg, const float* __restrict__ lneb,
    const float* __restrict__ attn_bi) {
    extern __shared__ float sm[];
    float* sW = sm;           // 4608
    float* sP = sW + 4608;    // 200
    float* a_t = sP + 200;    // max(8448, 128*68=8704)
    int t = threadIdx.x;
    for (int i = t; i < 4096; i += 128) { int d = i >> 6, c = i & 63; sW[d * 72 + wpos(c)] = We[i]; }
    if (t < 64) { sP[t] = be[t]; sP[64+t] = lneg[t]; sP[128+t] = lneb[t]; }
    if (t < 4) sP[192 + t] = attn_bi[2 * t];
    __syncthreads();
    int eb = blockIdx.x << 7;
    ln_transpose(ea, eb + t, t, sP + 64, sP + 128, a_t);
    __syncthreads();
    int lane = t & 31, wrp = t >> 5, cg = lane & 7, rgl = lane >> 3;
    int r0 = (wrp * 4 + rgl) * 8;
    u64 acc[8][4];
    init8x8(&sP[cg * 8], acc);
    gemm8x8<64, 132, 72>(a_t, sW + cg * 4, r0, acc);
    __syncthreads();
    float* e_s = a_t;  // reuse: [128 rows x 68], interleaved cols (wpos order)
    #pragma unroll
    for (int r = 0; r < 8; r++) {
        *(ulonglong2*)&e_s[(r0 + r) * 68 + cg * 4]      = make_ulonglong2(acc[r][0], acc[r][1]);
        *(ulonglong2*)&e_s[(r0 + r) * 68 + 32 + cg * 4] = make_ulonglong2(acc[r][2], acc[r][3]);
    }
    __syncthreads();
    {
        int e = eb + t;
        int src = ei[e], dst = ei[EE + e];
        const float4* qp = (const float4*)&g_q[(size_t)dst * 64];
        const float4* kp = (const float4*)&g_k[(size_t)src * 64];
        const float4* ep = (const float4*)&e_s[t * 68];
        float sc[4];
        #pragma unroll
        for (int h = 0; h < 4; h++) {
            float4 q0 = qp[4*h], q1 = qp[4*h+1], q2 = qp[4*h+2], q3 = qp[4*h+3];
            float4 k0 = kp[4*h], k1 = kp[4*h+1], k2 = kp[4*h+2], k3 = kp[4*h+3];
            // interleaved e order: [0-3]@2h, [4-7]@8+2h, [8-11]@2h+1, [12-15]@9+2h
            float4 e0 = ep[2*h], e1 = ep[8 + 2*h], e2 = ep[2*h + 1], e3 = ep[9 + 2*h];
            float dot = q0.x*k0.x*e0.x + q0.y*k0.y*e0.y + q0.z*k0.z*e0.z + q0.w*k0.w*e0.w
                      + q1.x*k1.x*e1.x + q1.y*k1.y*e1.y + q1.z*k1.z*e1.z + q1.w*k1.w*e1.w
                      + q2.x*k2.x*e2.x + q2.y*k2.y*e2.y + q2.z*k2.z*e2.z + q2.w*k2.w*e2.w
                      + q3.x*k3.x*e3.x + q3.y*k3.y*e3.y + q3.z*k3.z*e3.z + q3.w*k3.w*e3.w;
            sc[h] = dot * 0.25f + sP[192 + h];
        }
        *(float4*)&g_score[(size_t)e * 4] = make_float4(sc[0], sc[1], sc[2], sc[3]);
    }
}

// ---------------- K3: segment softmax + weighted gather ----------------
__global__ __launch_bounds__(256) void k_attn(const int* __restrict__ ei) {
    int gw = (blockIdx.x * blockDim.x + threadIdx.x) >> 5;
    int lane = threadIdx.x & 31;
    if (gw >= NN) return;
    int start = g_rs[gw], end = g_rs[gw + 1];
    const float NEG = __int_as_float(0xff800000);
    float m0 = NEG, m1 = NEG, m2 = NEG, m3 = NEG;
    for (int i = start + lane; i < end; i += 32) {
        float4 sc = ((const float4*)&g_score[g_elist[i] * 4])[0];
        m0 = fmaxf(m0, sc.x); m1 = fmaxf(m1, sc.y); m2 = fmaxf(m2, sc.z); m3 = fmaxf(m3, sc.w);
    }
    #pragma unroll
    for (int o = 16; o; o >>= 1) {
        m0 = fmaxf(m0, __shfl_xor_sync(~0u, m0, o));
        m1 = fmaxf(m1, __shfl_xor_sync(~0u, m1, o));
        m2 = fmaxf(m2, __shfl_xor_sync(~0u, m2, o));
        m3 = fmaxf(m3, __shfl_xor_sync(~0u, m3, o));
    }
    float s0 = 0.f, s1 = 0.f, s2 = 0.f, s3 = 0.f;
    for (int i = start + lane; i < end; i += 32) {
        float4 sc = ((const float4*)&g_score[g_elist[i] * 4])[0];
        s0 += __expf(sc.x - m0); s1 += __expf(sc.y - m1);
        s2 += __expf(sc.z - m2); s3 += __expf(sc.w - m3);
    }
    #pragma unroll
    for (int o = 16; o; o >>= 1) {
        s0 += __shfl_xor_sync(~0u, s0, o); s1 += __shfl_xor_sync(~0u, s1, o);
        s2 += __shfl_xor_sync(~0u, s2, o); s3 += __shfl_xor_sync(~0u, s3, o);
    }
    int h0 = lane >> 4;
    float mh0 = h0 ? m1 : m0, mh1 = h0 ? m3 : m2;
    float a0 = 0.f, a1 = 0.f;
    for (int i = start; i < end; i++) {
        int e = g_elist[i];
        int src = ei[e];
        float w0 = __expf(g_score[e * 4 + h0] - mh0);
        float w1 = __expf(g_score[e * 4 + 2 + h0] - mh1);
        a0 += w0 * g_v[src * 64 + lane];
        a1 += w1 * g_v[src * 64 + 32 + lane];
    }
    float d0 = (h0 ? s1 : s0) + 1e-16f, d1 = (h0 ? s3 : s2) + 1e-16f;
    g_attn[gw * 64 + lane] = a0 / d0;
    g_attn[gw * 64 + 32 + lane] = a1 / d1;
}

// ---------------- K4: Wo + gated residual + LN2 + FFN1 ----------------
__global__ __launch_bounds__(128) void k_mid(
    const float* __restrict__ x, const float* __restrict__ Wo, const float* __restrict__ bo,
    const float* __restrict__ skip, const float* __restrict__ ln2g, const float* __restrict__ ln2b,
    const float* __restrict__ W1, const float* __restrict__ b1) {
    extern __shared__ float sm[];
    float* sW = sm;           // 9216 (Wo 4608, then W1 64x144)
    float* sP = sW + 9216;    // 320: bo 0-63, b1 64-191, g 192-255, b 256-319
    float* a_t = sP + 320;    // 64*132 = 8448
    int t = threadIdx.x;
    for (int i = t; i < 4096; i += 128) { int d = i >> 6, c = i & 63; sW[d * 72 + wpos(c)] = Wo[i]; }
    if (t < 64) { sP[t] = bo[t]; sP[192+t] = ln2g[t]; sP[256+t] = ln2b[t]; }
    if (t < 128) sP[64 + t] = b1[t];
    __syncthreads();
    int nb = blockIdx.x << 7;
    {   // transpose attn
        const float4* ap = (const float4*)(g_attn + (size_t)(nb + t) * 64);
        #pragma unroll
        for (int i = 0; i < 16; i++) {
            float4 f = ap[i];
            a_t[(4*i) * 132 + t] = f.x; a_t[(4*i+1) * 132 + t] = f.y;
            a_t[(4*i+2) * 132 + t] = f.z; a_t[(4*i+3) * 132 + t] = f.w;
        }
    }
    __syncthreads();
    int lane = t & 31, wrp = t >> 5, cg = lane & 7, rgl = lane >> 3;
    int r0 = (wrp * 4 + rgl) * 8;
    u64 hacc[8][4];
    init8x8(&sP[cg * 8], hacc);
    gemm8x8<64, 132, 72>(a_t, sW + cg * 4, r0, hacc);
    // gated residual + LN2 stats
    float gg = 1.0f / (1.0f + __expf(-skip[0]));
    float omg = 1.0f - gg;
    float mu8[8], inv8[8];
    #pragma unroll
    for (int r = 0; r < 8; r++) {
        const ulonglong2* xp = (const ulonglong2*)&x[(size_t)(nb + r0 + r) * 64 + cg * 8];
        ulonglong2 xa = xp[0], xb = xp[1];
        float2 o0 = upk(hacc[r][0]), o1 = upk(hacc[r][1]), o2 = upk(hacc[r][2]), o3 = upk(hacc[r][3]);
        float2 x0 = upk(xa.x), x1 = upk(xa.y), x2 = upk(xb.x), x3 = upk(xb.y);
        float hs[8] = {gg*o0.x + omg*x0.x, gg*o0.y + omg*x0.y, gg*o1.x + omg*x1.x, gg*o1.y + omg*x1.y,
                       gg*o2.x + omg*x2.x, gg*o2.y + omg*x2.y, gg*o3.x + omg*x3.x, gg*o3.y + omg*x3.y};
        ulonglong2* hp = (ulonglong2*)&g_h1[(size_t)(nb + r0 + r) * 64 + cg * 8];
        hp[0] = make_ulonglong2(pk(hs[0], hs[1]), pk(hs[2], hs[3]));
        hp[1] = make_ulonglong2(pk(hs[4], hs[5]), pk(hs[6], hs[7]));
        hacc[r][0] = pk(hs[0], hs[1]); hacc[r][1] = pk(hs[2], hs[3]);
        hacc[r][2] = pk(hs[4], hs[5]); hacc[r][3] = pk(hs[6], hs[7]);
        float s = 0.f, ss = 0.f;
        #pragma unroll
        for (int j = 0; j < 8; j++) { s += hs[j]; ss += hs[j] * hs[j]; }
        s += __shfl_xor_sync(~0u, s, 1); ss += __shfl_xor_sync(~0u, ss, 1);
        s += __shfl_xor_sync(~0u, s, 2); ss += __shfl_xor_sync(~0u, ss, 2);
        s += __shfl_xor_sync(~0u, s, 4); ss += __shfl_xor_sync(~0u, ss, 4);
        float mu = s * 0.015625f;
        mu8[r] = mu;
        inv8[r] = rsqrtf(ss * 0.015625f - mu * mu + 1e-5f);
    }
    __syncthreads();  // done reading a_t (attn) and sW (Wo)
    // write hn2 transposed; load W1
    #pragma unroll
    for (int r = 0; r < 8; r++) {
        #pragma unroll
        for (int cp = 0; cp < 4; cp++) {
            float2 f = upk(hacc[r][cp]);
            int c0 = cg * 8 + 2 * cp;
            a_t[c0 * 132 + r0 + r]       = (f.x - mu8[r]) * inv8[r] * sP[192 + c0]     + sP[256 + c0];
            a_t[(c0 + 1) * 132 + r0 + r] = (f.y - mu8[r]) * inv8[r] * sP[192 + c0 + 1] + sP[256 + c0 + 1];
        }
    }
    for (int i = t; i < 8192; i += 128) {
        int d = i >> 7, c = i & 127;
        sW[d * 144 + (c >> 6) * 72 + wpos(c & 63)] = W1[i];
    }
    __syncthreads();
    // FFN1: two 64-col chunks
    #pragma unroll 1
    for (int ch = 0; ch < 2; ch++) {
        u64 macc[8][4];
        init8x8(&sP[64 + ch * 64 + cg * 8], macc);
        gemm8x8<64, 132, 144>(a_t, sW + ch * 72 + cg * 4, r0, macc);
        #pragma unroll
        for (int r = 0; r < 8; r++) {
            float2 f0 = upk(macc[r][0]), f1 = upk(macc[r][1]), f2 = upk(macc[r][2]), f3 = upk(macc[r][3]);
            ulonglong2* mp = (ulonglong2*)&g_m[(size_t)(nb + r0 + r) * 128 + ch * 64 + cg * 8];
            mp[0] = make_ulonglong2(pk(fmaxf(f0.x,0.f), fmaxf(f0.y,0.f)), pk(fmaxf(f1.x,0.f), fmaxf(f1.y,0.f)));
            mp[1] = make_ulonglong2(pk(fmaxf(f2.x,0.f), fmaxf(f2.y,0.f)), pk(fmaxf(f3.x,0.f), fmaxf(f3.y,0.f)));
        }
    }
}

// ---------------- K5: FFN2: out = h1 + b2 + m @ W2 ----------------
__global__ __launch_bounds__(128) void k_ffn2(
    const float* __restrict__ W2, const float* __restrict__ b2, float* __restrict__ outp) {
    extern __shared__ float sm[];
    float* sW = sm;           // 128*72 = 9216
    float* sP = sW + 9216;    // 64
    float* a_t = sP + 64;     // 128*132 = 16896
    int t = threadIdx.x;
    for (int i = t; i < 8192; i += 128) { int m = i >> 6, c = i & 63; sW[m * 72 + wpos(c)] = W2[i]; }
    if (t < 64) sP[t] = b2[t];
    int nb = blockIdx.x << 7;
    {   // transpose m
        const float4* mp = (const float4*)(g_m + (size_t)(nb + t) * 128);
        #pragma unroll
        for (int i = 0; i < 32; i++) {
            float4 f = mp[i];
            a_t[(4*i) * 132 + t] = f.x; a_t[(4*i+1) * 132 + t] = f.y;
            a_t[(4*i+2) * 132 + t] = f.z; a_t[(4*i+3) * 132 + t] = f.w;
        }
    }
    __syncthreads();
    int lane = t & 31, wrp = t >> 5, cg = lane & 7, rgl = lane >> 3;
    int r0 = (wrp * 4 + rgl) * 8;
    u64 acc[8][4];
    #pragma unroll
    for (int r = 0; r < 8; r++) {
        const float4* hp = (const float4*)&g_h1[(size_t)(nb + r0 + r) * 64 + cg * 8];
        float4 ha = hp[0], hb = hp[1];
        acc[r][0] = pk(ha.x + sP[cg*8+0], ha.y + sP[cg*8+1]);
        acc[r][1] = pk(ha.z + sP[cg*8+2], ha.w + sP[cg*8+3]);
        acc[r][2] = pk(hb.x + sP[cg*8+4], hb.y + sP[cg*8+5]);
        acc[r][3] = pk(hb.z + sP[cg*8+6], hb.w + sP[cg*8+7]);
    }
    gemm8x8<128, 132, 72>(a_t, sW + cg * 4, r0, acc);
    store8x8(outp + (size_t)nb * 64 + cg * 8, 64, r0, acc);
}

// ---------------- launch ----------------
extern "C" void kernel_launch(void* const* d_in, const int* in_sizes, int n_in,
                              void* d_out, int out_size) {
    const float* x    = (const float*)d_in[0];
    const int*   ei   = (const int*)  d_in[1];
    const float* ea   = (const float*)d_in[2];
    const float* Wq   = (const float*)d_in[3];
    const float* bq   = (const float*)d_in[4];
    const float* Wk   = (const float*)d_in[5];
    const float* bk   = (const float*)d_in[6];
    const float* Wv   = (const float*)d_in[7];
    const float* bv   = (const float*)d_in[8];
    const float* We   = (const float*)d_in[9];
    const float* be   = (const float*)d_in[10];
    const float* Wo   = (const float*)d_in[11];
    const float* bo   = (const float*)d_in[12];
    const float* edge_w = (const float*)d_in[13];
    const float* msg_w  = (const float*)d_in[14];
    const float* skip   = (const float*)d_in[15];
    const float* ln1g = (const float*)d_in[16];
    const float* ln1b = (const float*)d_in[17];
    const float* lneg = (const float*)d_in[18];
    const float* lneb = (const float*)d_in[19];
    const float* ln2g = (const float*)d_in[20];
    const float* ln2b = (const float*)d_in[21];
    const float* W1   = (const float*)d_in[22];
    const float* b1   = (const float*)d_in[23];
    const float* W2   = (const float*)d_in[24];
    const float* b2   = (const float*)d_in[25];
    const float* attn_bi = (const float*)d_in[26];
    float* out = (float*)d_out;

    int sm_node = (13824 + 320 + 8448) * 4;          // 90368
    int sm_edge = (4608 + 200 + 8704) * 4;           // 54048
    int sm_mid  = (9216 + 320 + 8448) * 4;           // 71936
    int sm_f2   = (9216 + 64 + 16896) * 4;           // 104704
    cudaFuncSetAttribute(k_node, cudaFuncAttributeMaxDynamicSharedMemorySize, sm_node);
    cudaFuncSetAttribute(k_edge, cudaFuncAttributeMaxDynamicSharedMemorySize, sm_edge);
    cudaFuncSetAttribute(k_mid,  cudaFuncAttributeMaxDynamicSharedMemorySize, sm_mid);
    cudaFuncSetAttribute(k_ffn2, cudaFuncAttributeMaxDynamicSharedMemorySize, sm_f2);

    k_zero_cnt<<<NN / 256, 256>>>();
    k_count<<<EE / 256, 256>>>(ei);
    k_scan<<<1, 1024>>>();
    k_scatter<<<EE / 256, 256>>>(ei);
    k_prep<<<1, 256>>>(Wk, bk, Wv, bv, edge_w, msg_w);

    k_node<<<NN / 128, 128, sm_node>>>(x, Wq, bq, ln1g, ln1b);
    k_edge<<<EE / 128, 128, sm_edge>>>(ea, ei, We, be, lneg, lneb, attn_bi);
    k_attn<<<(NN * 32) / 256, 256>>>(ei);
    k_mid<<<NN / 128, 128, sm_mid>>>(x, Wo, bo, skip, ln2g, ln2b, W1, b1);
    k_ffn2<<<NN / 128, 128, sm_f2>>>(W2, b2, out);
}

// round 7
// speedup vs baseline: 1.5687x; 1.1639x over previous
#include <cuda_runtime.h>
#include <math.h>

#define NN 65536
#define EE 524288
typedef unsigned long long u64;
typedef unsigned int u32;

__device__ __forceinline__ u64 pk(float x, float y) { u64 r; asm("mov.b64 %0,{%1,%2};" : "=l"(r) : "f"(x), "f"(y)); return r; }
__device__ __forceinline__ float2 upk(u64 v) { float2 f; asm("mov.b64 {%0,%1},%2;" : "=f"(f.x), "=f"(f.y) : "l"(v)); return f; }
__device__ __forceinline__ void fma2(u64& a, u64 b, u64 c) { asm("fma.rn.f32x2 %0,%1,%2,%0;" : "+l"(a) : "l"(b), "l"(c)); }
__device__ __forceinline__ int wpos(int c) { return ((c & 4) << 3) | ((c >> 3) << 2) | (c & 3); }

__device__ __forceinline__ void tf32split(float v, float& hi, float& lo) {
    u32 u; asm("cvt.rna.tf32.f32 %0, %1;" : "=r"(u) : "f"(v));
    hi = __uint_as_float(u); lo = v - hi;
}
__device__ __forceinline__ void mma8(float* d, const u32* a, const u32* b) {
    asm volatile("mma.sync.aligned.m16n8k8.row.col.f32.tf32.tf32.f32 "
        "{%0,%1,%2,%3}, {%4,%5,%6,%7}, {%8,%9}, {%0,%1,%2,%3};"
        : "+f"(d[0]), "+f"(d[1]), "+f"(d[2]), "+f"(d[3])
        : "r"(a[0]), "r"(a[1]), "r"(a[2]), "r"(a[3]), "r"(b[0]), "r"(b[1]));
}

// ---------------- scratch ----------------
__device__ float g_q[NN * 64];
__device__ float g_k[NN * 64];
__device__ float g_v[NN * 64];
__device__ float g_attn[NN * 64];
__device__ float g_h1[NN * 64];
__device__ float g_m[NN * 128];
__device__ float g_score[EE * 4];
__device__ float g_WkE[64 * 64];
__device__ float g_WvE[64 * 64];
__device__ float g_bkE[64];
__device__ float g_bvE[64];
__device__ int   g_cnt[NN];
__device__ int   g_cur[NN];
__device__ int   g_rs[NN + 1];
__device__ int   g_elist[EE];

// ---------------- CSR ----------------
__global__ void k_zero_cnt() { int i = blockIdx.x * 256 + threadIdx.x; if (i < NN) g_cnt[i] = 0; }
__global__ void k_count(const int* __restrict__ ei) {
    int e = blockIdx.x * 256 + threadIdx.x;
    if (e < EE) atomicAdd(&g_cnt[ei[EE + e]], 1);
}
__global__ void k_scan() {
    __shared__ int sb[1024];
    int t = threadIdx.x, base = t * 64, s = 0;
    for (int j = 0; j < 64; j++) s += g_cnt[base + j];
    sb[t] = s;
    __syncthreads();
    for (int off = 1; off < 1024; off <<= 1) {
        int v = (t >= off) ? sb[t - off] : 0;
        __syncthreads(); sb[t] += v; __syncthreads();
    }
    int run = sb[t] - s;
    for (int j = 0; j < 64; j++) { g_rs[base + j] = run; g_cur[base + j] = run; run += g_cnt[base + j]; }
    if (t == 1023) g_rs[NN] = run;
}
__global__ void k_scatter(const int* __restrict__ ei) {
    int e = blockIdx.x * 256 + threadIdx.x;
    if (e < EE) { int d = ei[EE + e]; g_elist[atomicAdd(&g_cur[d], 1)] = e; }
}

// ---------------- prep: fold head rotations into Wk/Wv ----------------
__global__ void k_prep(const float* __restrict__ Wk, const float* __restrict__ bk,
                       const float* __restrict__ Wv, const float* __restrict__ bv,
                       const float* __restrict__ ew, const float* __restrict__ mw) {
    int i = blockIdx.x * 256 + threadIdx.x;   // 4096 elements
    int d = i >> 6, hc = i & 63, h = hc >> 4, c = hc & 15;
    float sk = 0.f, sv = 0.f;
    #pragma unroll
    for (int d2 = 0; d2 < 16; d2++) {
        sk += Wk[d * 64 + h * 16 + d2] * ew[h * 256 + d2 * 16 + c];
        sv += Wv[d * 64 + h * 16 + d2] * mw[h * 256 + d2 * 16 + c];
    }
    g_WkE[i] = sk; g_WvE[i] = sv;
    if (blockIdx.x == 0 && threadIdx.x < 64) {
        int t = threadIdx.x, hh = t >> 4, cc = t & 15;
        float bkv = 0.f, bvv = 0.f;
        #pragma unroll
        for (int d2 = 0; d2 < 16; d2++) {
            bkv += bk[hh * 16 + d2] * ew[hh * 256 + d2 * 16 + cc];
            bvv += bv[hh * 16 + d2] * mw[hh * 256 + d2 * 16 + cc];
        }
        g_bkE[t] = bkv; g_bvE[t] = bvv;
    }
}

// ---------------- tf32 mma GEMM core: 128 rows x 64 cols, K=64, 4 warps ----------------
#define SWS 72
#define SAS 68
__device__ __forceinline__ void mma_gemm(const float* __restrict__ sWh, const float* __restrict__ sWl,
                                         const float* __restrict__ sAh, const float* __restrict__ sAl,
                                         int lane, int w, float acc[2][8][4]) {
    int g = lane >> 2, tig = lane & 3;
    for (int k0 = 0; k0 < 64; k0 += 8) {
        u32 ah[2][4], al[2][4];
        #pragma unroll
        for (int mt = 0; mt < 2; mt++) {
            int R = w * 32 + mt * 16;
            ah[mt][0] = __float_as_uint(sAh[(R + g) * SAS + k0 + tig]);
            ah[mt][1] = __float_as_uint(sAh[(R + g + 8) * SAS + k0 + tig]);
            ah[mt][2] = __float_as_uint(sAh[(R + g) * SAS + k0 + tig + 4]);
            ah[mt][3] = __float_as_uint(sAh[(R + g + 8) * SAS + k0 + tig + 4]);
            al[mt][0] = __float_as_uint(sAl[(R + g) * SAS + k0 + tig]);
            al[mt][1] = __float_as_uint(sAl[(R + g + 8) * SAS + k0 + tig]);
            al[mt][2] = __float_as_uint(sAl[(R + g) * SAS + k0 + tig + 4]);
            al[mt][3] = __float_as_uint(sAl[(R + g + 8) * SAS + k0 + tig + 4]);
        }
        #pragma unroll
        for (int n = 0; n < 8; n++) {
            u32 bh[2], bl[2];
            bh[0] = __float_as_uint(sWh[(k0 + tig) * SWS + n * 8 + g]);
            bh[1] = __float_as_uint(sWh[(k0 + tig + 4) * SWS + n * 8 + g]);
            bl[0] = __float_as_uint(sWl[(k0 + tig) * SWS + n * 8 + g]);
            bl[1] = __float_as_uint(sWl[(k0 + tig + 4) * SWS + n * 8 + g]);
            #pragma unroll
            for (int mt = 0; mt < 2; mt++) {
                mma8(acc[mt][n], ah[mt], bh);
                mma8(acc[mt][n], al[mt], bh);
                mma8(acc[mt][n], ah[mt], bl);
            }
        }
    }
}
__device__ __forceinline__ void bias_init(const float* bias, int lane, float acc[2][8][4]) {
    int tig = lane & 3;
    #pragma unroll
    for (int n = 0; n < 8; n++) {
        float b0 = bias[n * 8 + 2 * tig], b1 = bias[n * 8 + 2 * tig + 1];
        #pragma unroll
        for (int mt = 0; mt < 2; mt++) {
            acc[mt][n][0] = b0; acc[mt][n][1] = b1; acc[mt][n][2] = b0; acc[mt][n][3] = b1;
        }
    }
}
__device__ __forceinline__ void load_wsplit(const float* __restrict__ W, float* sWh, float* sWl, int t) {
    for (int i = t; i < 4096; i += 128) {
        int k = i >> 6, n = i & 63;
        float hi, lo; tf32split(W[i], hi, lo);
        sWh[k * SWS + n] = hi; sWl[k * SWS + n] = lo;
    }
}
__device__ __forceinline__ void ln_split_row(const float* __restrict__ in, int n, int t,
                                             const float* gv, const float* bv, float* sAh, float* sAl) {
    const float4* xp = (const float4*)(in + (size_t)n * 64);
    float v[64];
    #pragma unroll
    for (int i = 0; i < 16; i++) { float4 f = xp[i]; v[4*i] = f.x; v[4*i+1] = f.y; v[4*i+2] = f.z; v[4*i+3] = f.w; }
    float s = 0.f, ss = 0.f;
    #pragma unroll
    for (int i = 0; i < 64; i++) { s += v[i]; ss += v[i] * v[i]; }
    float mu = s * 0.015625f;
    float inv = rsqrtf(ss * 0.015625f - mu * mu + 1e-5f);
    #pragma unroll
    for (int d = 0; d < 64; d++) {
        float val = (v[d] - mu) * inv * gv[d] + bv[d];
        float hi, lo; tf32split(val, hi, lo);
        sAh[t * SAS + d] = hi; sAl[t * SAS + d] = lo;
    }
}

// ---------------- K1: node LN + QKV via mma (3 weight chunks) ----------------
__global__ __launch_bounds__(128) void k_node(
    const float* __restrict__ x, const float* __restrict__ Wq, const float* __restrict__ bq,
    const float* __restrict__ ln1g, const float* __restrict__ ln1b) {
    extern __shared__ float sm[];
    float* sWh = sm;
    float* sWl = sWh + 64 * SWS;
    float* sAh = sWl + 64 * SWS;
    float* sAl = sAh + 128 * SAS;
    float* sP  = sAl + 128 * SAS;   // 320
    int t = threadIdx.x, lane = t & 31, w = t >> 5;
    load_wsplit(Wq, sWh, sWl, t);
    if (t < 64) { sP[t] = bq[t]; sP[64+t] = g_bkE[t]; sP[128+t] = g_bvE[t]; sP[192+t] = ln1g[t]; sP[256+t] = ln1b[t]; }
    __syncthreads();
    int nb = blockIdx.x << 7;
    ln_split_row(x, nb + t, t, sP + 192, sP + 256, sAh, sAl);
    __syncthreads();
    int g = lane >> 2, tig = lane & 3;
    for (int ch = 0; ch < 3; ch++) {
        if (ch) {
            __syncthreads();
            load_wsplit(ch == 1 ? g_WkE : g_WvE, sWh, sWl, t);
            __syncthreads();
        }
        float acc[2][8][4];
        bias_init(sP + ch * 64, lane, acc);
        mma_gemm(sWh, sWl, sAh, sAl, lane, w, acc);
        float* ob = (ch == 0 ? g_q : (ch == 1 ? g_k : g_v)) + (size_t)nb * 64;
        #pragma unroll
        for (int mt = 0; mt < 2; mt++) {
            #pragma unroll
            for (int half = 0; half < 2; half++) {
                int r = w * 32 + mt * 16 + g + half * 8;
                #pragma unroll
                for (int n = 0; n < 8; n++)
                    *(float2*)(ob + (size_t)r * 64 + n * 8 + 2 * tig) =
                        make_float2(acc[mt][n][half * 2], acc[mt][n][half * 2 + 1]);
            }
        }
    }
}

// ---------------- K2: edge LN + e-proj via mma + scores ----------------
__global__ __launch_bounds__(128) void k_edge(
    const float* __restrict__ ea, const int* __restrict__ ei,
    const float* __restrict__ We, const float* __restrict__ be,
    const float* __restrict__ lneg, const float* __restrict__ lneb,
    const float* __restrict__ attn_bi) {
    extern __shared__ float sm[];
    float* sWh = sm;
    float* sWl = sWh + 64 * SWS;
    float* sAh = sWl + 64 * SWS;
    float* sAl = sAh + 128 * SAS;
    float* sP  = sAl + 128 * SAS;   // 200
    int t = threadIdx.x, lane = t & 31, w = t >> 5;
    load_wsplit(We, sWh, sWl, t);
    if (t < 64) { sP[t] = be[t]; sP[64+t] = lneg[t]; sP[128+t] = lneb[t]; }
    if (t < 4) sP[192 + t] = attn_bi[2 * t];
    __syncthreads();
    int eb = blockIdx.x << 7;
    ln_split_row(ea, eb + t, t, sP + 64, sP + 128, sAh, sAl);
    __syncthreads();
    int g = lane >> 2, tig = lane & 3;
    float acc[2][8][4];
    bias_init(sP, lane, acc);
    mma_gemm(sWh, sWl, sAh, sAl, lane, w, acc);
    float bi0 = sP[192], bi1 = sP[193], bi2 = sP[194], bi3 = sP[195];
    #pragma unroll
    for (int mt = 0; mt < 2; mt++) {
        #pragma unroll
        for (int half = 0; half < 2; half++) {
            int r = w * 32 + mt * 16 + g + half * 8;
            int e = eb + r;
            int src = ei[e], dst = ei[EE + e];
            const float* qb = g_q + (size_t)dst * 64;
            const float* kb = g_k + (size_t)src * 64;
            float h0 = 0.f, h1 = 0.f, h2 = 0.f, h3 = 0.f;
            #pragma unroll
            for (int n = 0; n < 8; n++) {
                int c = n * 8 + 2 * tig;
                float2 qv = *(const float2*)(qb + c);
                float2 kv = *(const float2*)(kb + c);
                float p = qv.x * kv.x * acc[mt][n][half * 2] + qv.y * kv.y * acc[mt][n][half * 2 + 1];
                if (n < 2) h0 += p; else if (n < 4) h1 += p; else if (n < 6) h2 += p; else h3 += p;
            }
            h0 += __shfl_xor_sync(~0u, h0, 1); h0 += __shfl_xor_sync(~0u, h0, 2);
            h1 += __shfl_xor_sync(~0u, h1, 1); h1 += __shfl_xor_sync(~0u, h1, 2);
            h2 += __shfl_xor_sync(~0u, h2, 1); h2 += __shfl_xor_sync(~0u, h2, 2);
            h3 += __shfl_xor_sync(~0u, h3, 1); h3 += __shfl_xor_sync(~0u, h3, 2);
            if (tig == 0)
                *(float4*)&g_score[(size_t)e * 4] =
                    make_float4(h0 * 0.25f + bi0, h1 * 0.25f + bi1, h2 * 0.25f + bi2, h3 * 0.25f + bi3);
        }
    }
}

// ---------------- K3: segment softmax + weighted gather ----------------
__global__ __launch_bounds__(256) void k_attn(const int* __restrict__ ei) {
    int gw = (blockIdx.x * blockDim.x + threadIdx.x) >> 5;
    int lane = threadIdx.x & 31;
    if (gw >= NN) return;
    int start = g_rs[gw], end = g_rs[gw + 1];
    const float NEG = __int_as_float(0xff800000);
    float m0 = NEG, m1 = NEG, m2 = NEG, m3 = NEG;
    for (int i = start + lane; i < end; i += 32) {
        float4 sc = ((const float4*)&g_score[g_elist[i] * 4])[0];
        m0 = fmaxf(m0, sc.x); m1 = fmaxf(m1, sc.y); m2 = fmaxf(m2, sc.z); m3 = fmaxf(m3, sc.w);
    }
    #pragma unroll
    for (int o = 16; o; o >>= 1) {
        m0 = fmaxf(m0, __shfl_xor_sync(~0u, m0, o));
        m1 = fmaxf(m1, __shfl_xor_sync(~0u, m1, o));
        m2 = fmaxf(m2, __shfl_xor_sync(~0u, m2, o));
        m3 = fmaxf(m3, __shfl_xor_sync(~0u, m3, o));
    }
    float s0 = 0.f, s1 = 0.f, s2 = 0.f, s3 = 0.f;
    for (int i = start + lane; i < end; i += 32) {
        float4 sc = ((const float4*)&g_score[g_elist[i] * 4])[0];
        s0 += __expf(sc.x - m0); s1 += __expf(sc.y - m1);
        s2 += __expf(sc.z - m2); s3 += __expf(sc.w - m3);
    }
    #pragma unroll
    for (int o = 16; o; o >>= 1) {
        s0 += __shfl_xor_sync(~0u, s0, o); s1 += __shfl_xor_sync(~0u, s1, o);
        s2 += __shfl_xor_sync(~0u, s2, o); s3 += __shfl_xor_sync(~0u, s3, o);
    }
    int h0 = lane >> 4;
    float mh0 = h0 ? m1 : m0, mh1 = h0 ? m3 : m2;
    float a0 = 0.f, a1 = 0.f;
    for (int i = start; i < end; i++) {
        int e = g_elist[i];
        int src = ei[e];
        float w0 = __expf(g_score[e * 4 + h0] - mh0);
        float w1 = __expf(g_score[e * 4 + 2 + h0] - mh1);
        a0 += w0 * g_v[src * 64 + lane];
        a1 += w1 * g_v[src * 64 + 32 + lane];
    }
    float d0 = (h0 ? s1 : s0) + 1e-16f, d1 = (h0 ? s3 : s2) + 1e-16f;
    g_attn[gw * 64 + lane] = a0 / d0;
    g_attn[gw * 64 + 32 + lane] = a1 / d1;
}

// ---------------- scalar 8x8 helpers (k_mid / k_ffn2) ----------------
__device__ __forceinline__ void init8x8(const float* b, u64 acc[8][4]) {
    #pragma unroll
    for (int cp = 0; cp < 4; cp++) {
        u64 bi = pk(b[2 * cp], b[2 * cp + 1]);
        #pragma unroll
        for (int r = 0; r < 8; r++) acc[r][cp] = bi;
    }
}
template <int K, int AS, int WS>
__device__ __forceinline__ void gemm8x8(const float* __restrict__ a_t,
                                        const float* __restrict__ sWb, int r0, u64 acc[8][4]) {
    #pragma unroll 4
    for (int d = 0; d < K; d++) {
        ulonglong2 wA = *(const ulonglong2*)(sWb + d * WS);
        ulonglong2 wB = *(const ulonglong2*)(sWb + d * WS + 32);
        float4 aA = *(const float4*)(a_t + d * AS + r0);
        float4 aB = *(const float4*)(a_t + d * AS + r0 + 4);
        float av[8] = {aA.x, aA.y, aA.z, aA.w, aB.x, aB.y, aB.z, aB.w};
        #pragma unroll
        for (int r = 0; r < 8; r++) {
            u64 a2 = pk(av[r], av[r]);
            fma2(acc[r][0], a2, wA.x);
            fma2(acc[r][1], a2, wA.y);
            fma2(acc[r][2], a2, wB.x);
            fma2(acc[r][3], a2, wB.y);
        }
    }
}
__device__ __forceinline__ void store8x8(float* base, int rstride, int r0, u64 acc[8][4]) {
    #pragma unroll
    for (int r = 0; r < 8; r++) {
        ulonglong2* o = (ulonglong2*)(base + (size_t)(r0 + r) * rstride);
        o[0] = make_ulonglong2(acc[r][0], acc[r][1]);
        o[1] = make_ulonglong2(acc[r][2], acc[r][3]);
    }
}

// ---------------- K4: Wo + gated residual + LN2 + FFN1 ----------------
__global__ __launch_bounds__(128) void k_mid(
    const float* __restrict__ x, const float* __restrict__ Wo, const float* __restrict__ bo,
    const float* __restrict__ skip, const float* __restrict__ ln2g, const float* __restrict__ ln2b,
    const float* __restrict__ W1, const float* __restrict__ b1) {
    extern __shared__ float sm[];
    float* sW = sm;           // 9216
    float* sP = sW + 9216;    // 320
    float* a_t = sP + 320;    // 64*132
    int t = threadIdx.x;
    for (int i = t; i < 4096; i += 128) { int d = i >> 6, c = i & 63; sW[d * 72 + wpos(c)] = Wo[i]; }
    if (t < 64) { sP[t] = bo[t]; sP[192+t] = ln2g[t]; sP[256+t] = ln2b[t]; }
    if (t < 128) sP[64 + t] = b1[t];
    __syncthreads();
    int nb = blockIdx.x << 7;
    {
        const float4* ap = (const float4*)(g_attn + (size_t)(nb + t) * 64);
        #pragma unroll
        for (int i = 0; i < 16; i++) {
            float4 f = ap[i];
            a_t[(4*i) * 132 + t] = f.x; a_t[(4*i+1) * 132 + t] = f.y;
            a_t[(4*i+2) * 132 + t] = f.z; a_t[(4*i+3) * 132 + t] = f.w;
        }
    }
    __syncthreads();
    int lane = t & 31, wrp = t >> 5, cg = lane & 7, rgl = lane >> 3;
    int r0 = (wrp * 4 + rgl) * 8;
    u64 hacc[8][4];
    init8x8(&sP[cg * 8], hacc);
    gemm8x8<64, 132, 72>(a_t, sW + cg * 4, r0, hacc);
    float gg = 1.0f / (1.0f + __expf(-skip[0]));
    float omg = 1.0f - gg;
    float mu8[8], inv8[8];
    #pragma unroll
    for (int r = 0; r < 8; r++) {
        const ulonglong2* xp = (const ulonglong2*)&x[(size_t)(nb + r0 + r) * 64 + cg * 8];
        ulonglong2 xa = xp[0], xb = xp[1];
        float2 o0 = upk(hacc[r][0]), o1 = upk(hacc[r][1]), o2 = upk(hacc[r][2]), o3 = upk(hacc[r][3]);
        float2 x0 = upk(xa.x), x1 = upk(xa.y), x2 = upk(xb.x), x3 = upk(xb.y);
        float hs[8] = {gg*o0.x + omg*x0.x, gg*o0.y + omg*x0.y, gg*o1.x + omg*x1.x, gg*o1.y + omg*x1.y,
                       gg*o2.x + omg*x2.x, gg*o2.y + omg*x2.y, gg*o3.x + omg*x3.x, gg*o3.y + omg*x3.y};
        ulonglong2* hp = (ulonglong2*)&g_h1[(size_t)(nb + r0 + r) * 64 + cg * 8];
        hp[0] = make_ulonglong2(pk(hs[0], hs[1]), pk(hs[2], hs[3]));
        hp[1] = make_ulonglong2(pk(hs[4], hs[5]), pk(hs[6], hs[7]));
        hacc[r][0] = pk(hs[0], hs[1]); hacc[r][1] = pk(hs[2], hs[3]);
        hacc[r][2] = pk(hs[4], hs[5]); hacc[r][3] = pk(hs[6], hs[7]);
        float s = 0.f, ss = 0.f;
        #pragma unroll
        for (int j = 0; j < 8; j++) { s += hs[j]; ss += hs[j] * hs[j]; }
        s += __shfl_xor_sync(~0u, s, 1); ss += __shfl_xor_sync(~0u, ss, 1);
        s += __shfl_xor_sync(~0u, s, 2); ss += __shfl_xor_sync(~0u, ss, 2);
        s += __shfl_xor_sync(~0u, s, 4); ss += __shfl_xor_sync(~0u, ss, 4);
        float mu = s * 0.015625f;
        mu8[r] = mu;
        inv8[r] = rsqrtf(ss * 0.015625f - mu * mu + 1e-5f);
    }
    __syncthreads();
    #pragma unroll
    for (int r = 0; r < 8; r++) {
        #pragma unroll
        for (int cp = 0; cp < 4; cp++) {
            float2 f = upk(hacc[r][cp]);
            int c0 = cg * 8 + 2 * cp;
            a_t[c0 * 132 + r0 + r]       = (f.x - mu8[r]) * inv8[r] * sP[192 + c0]     + sP[256 + c0];
            a_t[(c0 + 1) * 132 + r0 + r] = (f.y - mu8[r]) * inv8[r] * sP[192 + c0 + 1] + sP[256 + c0 + 1];
        }
    }
    for (int i = t; i < 8192; i += 128) {
        int d = i >> 7, c = i & 127;
        sW[d * 144 + (c >> 6) * 72 + wpos(c & 63)] = W1[i];
    }
    __syncthreads();
    for (int ch = 0; ch < 2; ch++) {
        u64 macc[8][4];
        init8x8(&sP[64 + ch * 64 + cg * 8], macc);
        gemm8x8<64, 132, 144>(a_t, sW + ch * 72 + cg * 4, r0, macc);
        #pragma unroll
        for (int r = 0; r < 8; r++) {
            float2 f0 = upk(macc[r][0]), f1 = upk(macc[r][1]), f2 = upk(macc[r][2]), f3 = upk(macc[r][3]);
            ulonglong2* mp = (ulonglong2*)&g_m[(size_t)(nb + r0 + r) * 128 + ch * 64 + cg * 8];
            mp[0] = make_ulonglong2(pk(fmaxf(f0.x,0.f), fmaxf(f0.y,0.f)), pk(fmaxf(f1.x,0.f), fmaxf(f1.y,0.f)));
            mp[1] = make_ulonglong2(pk(fmaxf(f2.x,0.f), fmaxf(f2.y,0.f)), pk(fmaxf(f3.x,0.f), fmaxf(f3.y,0.f)));
        }
    }
}

// ---------------- K5: FFN2 ----------------
__global__ __launch_bounds__(128) void k_ffn2(
    const float* __restrict__ W2, const float* __restrict__ b2, float* __restrict__ outp) {
    extern __shared__ float sm[];
    float* sW = sm;           // 9216
    float* sP = sW + 9216;    // 64
    float* a_t = sP + 64;     // 128*132
    int t = threadIdx.x;
    for (int i = t; i < 8192; i += 128) { int m = i >> 6, c = i & 63; sW[m * 72 + wpos(c)] = W2[i]; }
    if (t < 64) sP[t] = b2[t];
    int nb = blockIdx.x << 7;
    {
        const float4* mp = (const float4*)(g_m + (size_t)(nb + t) * 128);
        #pragma unroll
        for (int i = 0; i < 32; i++) {
            float4 f = mp[i];
            a_t[(4*i) * 132 + t] = f.x; a_t[(4*i+1) * 132 + t] = f.y;
            a_t[(4*i+2) * 132 + t] = f.z; a_t[(4*i+3) * 132 + t] = f.w;
        }
    }
    __syncthreads();
    int lane = t & 31, wrp = t >> 5, cg = lane & 7, rgl = lane >> 3;
    int r0 = (wrp * 4 + rgl) * 8;
    u64 acc[8][4];
    #pragma unroll
    for (int r = 0; r < 8; r++) {
        const float4* hp = (const float4*)&g_h1[(size_t)(nb + r0 + r) * 64 + cg * 8];
        float4 ha = hp[0], hb = hp[1];
        acc[r][0] = pk(ha.x + sP[cg*8+0], ha.y + sP[cg*8+1]);
        acc[r][1] = pk(ha.z + sP[cg*8+2], ha.w + sP[cg*8+3]);
        acc[r][2] = pk(hb.x + sP[cg*8+4], hb.y + sP[cg*8+5]);
        acc[r][3] = pk(hb.z + sP[cg*8+6], hb.w + sP[cg*8+7]);
    }
    gemm8x8<128, 132, 72>(a_t, sW + cg * 4, r0, acc);
    store8x8(outp + (size_t)nb * 64 + cg * 8, 64, r0, acc);
}

// ---------------- launch ----------------
extern "C" void kernel_launch(void* const* d_in, const int* in_sizes, int n_in,
                              void* d_out, int out_size) {
    const float* x    = (const float*)d_in[0];
    const int*   ei   = (const int*)  d_in[1];
    const float* ea   = (const float*)d_in[2];
    const float* Wq   = (const float*)d_in[3];
    const float* bq   = (const float*)d_in[4];
    const float* Wk   = (const float*)d_in[5];
    const float* bk   = (const float*)d_in[6];
    const float* Wv   = (const float*)d_in[7];
    const float* bv   = (const float*)d_in[8];
    const float* We   = (const float*)d_in[9];
    const float* be   = (const float*)d_in[10];
    const float* Wo   = (const float*)d_in[11];
    const float* bo   = (const float*)d_in[12];
    const float* edge_w = (const float*)d_in[13];
    const float* msg_w  = (const float*)d_in[14];
    const float* skip   = (const float*)d_in[15];
    const float* ln1g = (const float*)d_in[16];
    const float* ln1b = (const float*)d_in[17];
    const float* lneg = (const float*)d_in[18];
    const float* lneb = (const float*)d_in[19];
    const float* ln2g = (const float*)d_in[20];
    const float* ln2b = (const float*)d_in[21];
    const float* W1   = (const float*)d_in[22];
    const float* b1   = (const float*)d_in[23];
    const float* W2   = (const float*)d_in[24];
    const float* b2   = (const float*)d_in[25];
    const float* attn_bi = (const float*)d_in[26];
    float* out = (float*)d_out;

    int sm_qkv = (2 * 64 * SWS + 2 * 128 * SAS + 320) * 4;
    int sm_edge = (2 * 64 * SWS + 2 * 128 * SAS + 200) * 4;
    int sm_mid  = (9216 + 320 + 8448) * 4;
    int sm_f2   = (9216 + 64 + 16896) * 4;
    cudaFuncSetAttribute(k_node, cudaFuncAttributeMaxDynamicSharedMemorySize, sm_qkv);
    cudaFuncSetAttribute(k_edge, cudaFuncAttributeMaxDynamicSharedMemorySize, sm_edge);
    cudaFuncSetAttribute(k_mid,  cudaFuncAttributeMaxDynamicSharedMemorySize, sm_mid);
    cudaFuncSetAttribute(k_ffn2, cudaFuncAttributeMaxDynamicSharedMemorySize, sm_f2);

    // order chosen so the profiled launch slot (#4) is k_edge
    k_prep<<<16, 256>>>(Wk, bk, Wv, bv, edge_w, msg_w);
    k_node<<<NN / 128, 128, sm_qkv>>>(x, Wq, bq, ln1g, ln1b);
    k_zero_cnt<<<NN / 256, 256>>>();
    k_edge<<<EE / 128, 128, sm_edge>>>(ea, ei, We, be, lneg, lneb, attn_bi);
    k_count<<<EE / 256, 256>>>(ei);
    k_scan<<<1, 1024>>>();
    k_scatter<<<EE / 256, 256>>>(ei);
    k_attn<<<(NN * 32) / 256, 256>>>(ei);
    k_mid<<<NN / 128, 128, sm_mid>>>(x, Wo, bo, skip, ln2g, ln2b, W1, b1);
    k_ffn2<<<NN / 128, 128, sm_f2>>>(W2, b2, out);
}